// round 10
// baseline (speedup 1.0000x reference)
#include <cuda_runtime.h>
#include <cuda_bf16.h>
#include <cfloat>
#include <cstdint>

#define N_NODES 50000
#define N_EDGES 800000
#define HID 64
#define ZDIM 320
#define WSTRIDE 68                 // padded W row (64x68, zeros in pad)
#define WSZ (64 * WSTRIDE)
#define SCAN_BLK 98                // ceil(50000/512)
#define NPADZ 50016                // pad g_z rows so 32-node MLP tiles read safely

typedef unsigned long long ull;

// ---------------- device scratch ----------------
__device__ float g_u[N_NODES * HID];
__device__ float g_z[NPADZ * ZDIM];        // pad rows never written -> stay zero
__device__ int   g_cnt[N_NODES];           // INVARIANT: all-zero at kernel_launch entry
__device__ int   g_off[N_NODES + 1];
__device__ int   g_cur[N_NODES];
__device__ int   g_csr[N_EDGES];
__device__ int   g_bsum[SCAN_BLK];
__device__ float g_Wq[5 * WSZ];            // all 5 quantized layer weights
__device__ float g_w1P[320 * 128];         // paired [c/2][128] float2 layout
__device__ float g_w2P[128 * 128];
__device__ float g_w3P[128 * 64];

// ---------------- f32x2 helpers ----------------
__device__ __forceinline__ ull fma2(ull a, ull b, ull c) {
    ull d;
    asm("fma.rn.f32x2 %0, %1, %2, %3;" : "=l"(d) : "l"(a), "l"(b), "l"(c));
    return d;
}
__device__ __forceinline__ ull pack2(float lo, float hi) {
    ull r;
    asm("mov.b64 %0, {%1, %2};" : "=l"(r) : "f"(lo), "f"(hi));
    return r;
}
__device__ __forceinline__ float sum2(ull a) {
    float lo, hi;
    asm("mov.b64 {%0, %1}, %2;" : "=f"(lo), "=f"(hi) : "l"(a));
    return lo + hi;
}

// ---------------- prep: hist (blocks 0..3124) + fake-quant/transpose (3125..3289) ----------------
__global__ void k_prep(const int* __restrict__ ei,
                       const float* __restrict__ W0, const float* __restrict__ Ws,
                       const float* __restrict__ w1, const float* __restrict__ w2,
                       const float* __restrict__ w3) {
    int blk = blockIdx.x, tid = threadIdx.x;
    if (blk < 3125) {
        int e = blk * 256 + tid;
        if (e < N_EDGES) atomicAdd(&g_cnt[ei[N_EDGES + e]], 1);
        return;
    }
    int b = blk - 3125;
    if (b < 5) {
        __shared__ float red[256];
        const float* W = (b == 0) ? W0 : (Ws + (size_t)(b - 1) * 64 * 67);
        int cols = (b == 0) ? 4 : 67;
        int n = 64 * cols;
        float* dst = g_Wq + b * WSZ;

        float m = 0.f;
        for (int i = tid; i < n; i += 256) m = fmaxf(m, fabsf(W[i]));
        red[tid] = m;
        __syncthreads();
        for (int s = 128; s > 0; s >>= 1) {
            if (tid < s) red[tid] = fmaxf(red[tid], red[tid + s]);
            __syncthreads();
        }
        float sc = fmaxf(red[0] * (1.0f / 127.0f), 1e-8f);
        for (int i = tid; i < WSZ; i += 256) dst[i] = 0.0f;
        __syncthreads();
        for (int i = tid; i < n; i += 256) {
            int k = i / cols, c = i % cols;
            float q = rintf(W[i] / sc);
            q = fminf(fmaxf(q, -127.0f), 127.0f) * sc;
            dst[k * WSTRIDE + c] = q;
        }
    } else {
        int i = (b - 5) * 256 + tid;
        if (i < 40960) { int r = i / 320, c = i % 320; g_w1P[((c >> 1) * 128 + r) * 2 + (c & 1)] = w1[i]; }
        if (i < 16384) { int r = i / 128, c = i % 128; g_w2P[((c >> 1) * 128 + r) * 2 + (c & 1)] = w2[i]; }
        if (i <  8192) { int r = i / 128, c = i % 128; g_w3P[((c >> 1) * 64  + r) * 2 + (c & 1)] = w3[i]; }
    }
}

// ---------------- CSR scan ----------------
__global__ void k_scan_local() {
    __shared__ int wsums[16];
    int b = blockIdx.x, tid = threadIdx.x, lane = tid & 31, wid = tid >> 5;
    int i = b * 512 + tid;
    int v = (i < N_NODES) ? g_cnt[i] : 0;
    int x = v;
    #pragma unroll
    for (int o = 1; o < 32; o <<= 1) {
        int y = __shfl_up_sync(0xffffffffu, x, o);
        if (lane >= o) x += y;
    }
    if (lane == 31) wsums[wid] = x;
    __syncthreads();
    if (wid == 0 && lane < 16) {
        int w = wsums[lane];
        int xs = w;
        #pragma unroll
        for (int o = 1; o < 16; o <<= 1) {
            int y = __shfl_up_sync(0xffffu, xs, o);
            if (lane >= o) xs += y;
        }
        wsums[lane] = xs - w;
    }
    __syncthreads();
    int excl = x - v + wsums[wid];
    if (i < N_NODES) g_off[i] = excl;
    if (tid == 511) g_bsum[b] = excl + v;
}

__global__ void k_scan_add() {
    __shared__ int part[4];
    int b = blockIdx.x, tid = threadIdx.x, lane = tid & 31, wid = tid >> 5;
    int v = 0;
    if (tid < b) v = g_bsum[tid];      // b <= 97 < 128
    if (tid < 128) {
        #pragma unroll
        for (int o = 16; o > 0; o >>= 1) v += __shfl_xor_sync(0xffffffffu, v, o);
        if (lane == 0) part[wid] = v;
    }
    __syncthreads();
    int add = part[0] + part[1] + part[2] + part[3];
    int i = b * 512 + tid;
    if (i < N_NODES) {
        int o = g_off[i] + add;
        g_off[i] = o;
        g_cur[i] = o;
        g_cnt[i] = 0;   // restore zero-invariant for next replay
    }
    if (i == 0) g_off[N_NODES] = N_EDGES;
}

__global__ void k_scatter(const int* __restrict__ ei) {
    int e = blockIdx.x * blockDim.x + threadIdx.x;
    if (e < N_EDGES) {
        int d = ei[N_EDGES + e];
        int p = atomicAdd(&g_cur[d], 1);
        g_csr[p] = ei[e];
    }
}

// ---------------- layer-0 transform ----------------
__global__ __launch_bounds__(256) void k_transform0(const float* __restrict__ x,
                                                    const float* __restrict__ pos) {
    __shared__ float4 Wsh[64];
    __shared__ float  xs[32];
    __shared__ float  ps[96];
    int tid = threadIdx.x;
    int nbase = blockIdx.x * 32;
    if (tid < 64) {
        const float* wr = g_Wq + tid * WSTRIDE;
        Wsh[tid] = make_float4(wr[0], wr[1], wr[2], wr[3]);
    } else if (tid < 96) {
        int n = nbase + (tid - 64);
        xs[tid - 64] = (n < N_NODES) ? x[n] : 0.f;
    } else if (tid < 192) {
        int j = tid - 96;
        int gi = nbase * 3 + j;
        ps[j] = (gi < N_NODES * 3) ? pos[gi] : 0.f;
    }
    __syncthreads();
    int k = tid & 63, grp = tid >> 6;
    float4 w = Wsh[k];
    #pragma unroll
    for (int j = 0; j < 8; j++) {
        int nn = grp * 8 + j;
        int n = nbase + nn;
        if (n < N_NODES)
            g_u[(size_t)n * HID + k] = w.x * xs[nn] + w.y * ps[3 * nn] + w.z * ps[3 * nn + 1] + w.w * ps[3 * nn + 2];
    }
}

// ---------------- layers 1-4 transform ----------------
__global__ __launch_bounds__(256) void k_transform(const float* __restrict__ pos, int layer) {
    constexpr int C4 = 17;
    __shared__ float Wsh[WSZ];
    __shared__ float fsh[32][WSTRIDE];
    int tid = threadIdx.x;
    int k = tid & 63, grp = tid >> 6;
    const float* Wsrc = g_Wq + layer * WSZ;
    {
        const float4* s4 = (const float4*)Wsrc;
        float4* d4 = (float4*)Wsh;
        #pragma unroll
        for (int i = tid; i < WSZ / 4; i += 256) d4[i] = s4[i];
    }
    int nbase = blockIdx.x * 32;
    const float* h = g_z + (size_t)(layer - 1) * HID;
    #pragma unroll
    for (int i = tid; i < 32 * 64; i += 256) {
        int nn = i >> 6, c = i & 63;
        int gn = nbase + nn;
        fsh[nn][c] = (gn < N_NODES) ? h[(size_t)gn * ZDIM + c] : 0.f;
    }
    if (tid < 128) {
        int nn = tid >> 2, j = tid & 3;
        int gn = nbase + nn;
        float v = 0.f;
        if (j < 3 && gn < N_NODES) v = pos[gn * 3 + j];
        fsh[nn][64 + j] = v;
    }
    __syncthreads();
    ull w2r[C4 * 2];
    #pragma unroll
    for (int c4 = 0; c4 < C4; c4++) {
        ulonglong2 wv = *(const ulonglong2*)&Wsh[k * WSTRIDE + 4 * c4];
        w2r[2 * c4] = wv.x; w2r[2 * c4 + 1] = wv.y;
    }
    ull acc[8];
    #pragma unroll
    for (int j = 0; j < 8; j++) acc[j] = 0;
    #pragma unroll
    for (int c4 = 0; c4 < C4; c4++) {
        ull w01 = w2r[2 * c4], w23 = w2r[2 * c4 + 1];
        #pragma unroll
        for (int j = 0; j < 8; j++) {
            ulonglong2 f = *(const ulonglong2*)&fsh[grp * 8 + j][4 * c4];
            acc[j] = fma2(f.x, w01, acc[j]);
            acc[j] = fma2(f.y, w23, acc[j]);
        }
    }
    #pragma unroll
    for (int j = 0; j < 8; j++) {
        int n = nbase + grp * 8 + j;
        if (n < N_NODES) g_u[(size_t)n * HID + k] = sum2(acc[j]);
    }
}

// ---------------- aggregation: 2 nodes/warp, 16 lanes x float4 ----------------
__global__ __launch_bounds__(256) void k_aggregate(const float* __restrict__ pos,
                                                   const float* __restrict__ ln_g,
                                                   const float* __restrict__ ln_b,
                                                   int layer, int cols) {
    __shared__ float Wp[64][3];
    __shared__ float gs[64], bs[64];
    int tid = threadIdx.x;
    if (tid < 64) { gs[tid] = ln_g[layer * 64 + tid]; bs[tid] = ln_b[layer * 64 + tid]; }
    const float* Wsrc = g_Wq + layer * WSZ;
    for (int i = tid; i < 192; i += 256) {
        int k = i / 3, j = i % 3;
        Wp[k][j] = Wsrc[k * WSTRIDE + (cols - 3) + j];
    }
    __syncthreads();

    int wid = tid >> 5, lane = tid & 31;
    int half = lane >> 4, l16 = lane & 15;
    int n = blockIdx.x * 16 + wid * 2 + half;      // grid*16 == N_NODES exactly
    int s = g_off[n], e = g_off[n + 1];
    const float4* ubase = (const float4*)g_u;       // row = 16 float4

    float4 m = make_float4(-FLT_MAX, -FLT_MAX, -FLT_MAX, -FLT_MAX);
    int p = s;
    for (; p + 8 <= e; p += 8) {
        int i0 = g_csr[p],     i1 = g_csr[p + 1], i2 = g_csr[p + 2], i3 = g_csr[p + 3];
        int i4 = g_csr[p + 4], i5 = g_csr[p + 5], i6 = g_csr[p + 6], i7 = g_csr[p + 7];
        float4 a = __ldcg(&ubase[(size_t)i0 * 16 + l16]);
        float4 b = __ldcg(&ubase[(size_t)i1 * 16 + l16]);
        float4 c = __ldcg(&ubase[(size_t)i2 * 16 + l16]);
        float4 d = __ldcg(&ubase[(size_t)i3 * 16 + l16]);
        float4 f = __ldcg(&ubase[(size_t)i4 * 16 + l16]);
        float4 g = __ldcg(&ubase[(size_t)i5 * 16 + l16]);
        float4 h = __ldcg(&ubase[(size_t)i6 * 16 + l16]);
        float4 q = __ldcg(&ubase[(size_t)i7 * 16 + l16]);
        m.x = fmaxf(m.x, fmaxf(fmaxf(fmaxf(a.x, b.x), fmaxf(c.x, d.x)), fmaxf(fmaxf(f.x, g.x), fmaxf(h.x, q.x))));
        m.y = fmaxf(m.y, fmaxf(fmaxf(fmaxf(a.y, b.y), fmaxf(c.y, d.y)), fmaxf(fmaxf(f.y, g.y), fmaxf(h.y, q.y))));
        m.z = fmaxf(m.z, fmaxf(fmaxf(fmaxf(a.z, b.z), fmaxf(c.z, d.z)), fmaxf(fmaxf(f.z, g.z), fmaxf(h.z, q.z))));
        m.w = fmaxf(m.w, fmaxf(fmaxf(fmaxf(a.w, b.w), fmaxf(c.w, d.w)), fmaxf(fmaxf(f.w, g.w), fmaxf(h.w, q.w))));
    }
    for (; p + 4 <= e; p += 4) {
        int i0 = g_csr[p], i1 = g_csr[p + 1], i2 = g_csr[p + 2], i3 = g_csr[p + 3];
        float4 a = __ldcg(&ubase[(size_t)i0 * 16 + l16]);
        float4 b = __ldcg(&ubase[(size_t)i1 * 16 + l16]);
        float4 c = __ldcg(&ubase[(size_t)i2 * 16 + l16]);
        float4 d = __ldcg(&ubase[(size_t)i3 * 16 + l16]);
        m.x = fmaxf(fmaxf(fmaxf(m.x, a.x), fmaxf(b.x, c.x)), d.x);
        m.y = fmaxf(fmaxf(fmaxf(m.y, a.y), fmaxf(b.y, c.y)), d.y);
        m.z = fmaxf(fmaxf(fmaxf(m.z, a.z), fmaxf(b.z, c.z)), d.z);
        m.w = fmaxf(fmaxf(fmaxf(m.w, a.w), fmaxf(b.w, c.w)), d.w);
    }
    for (; p < e; p++) {
        int i0 = g_csr[p];
        float4 a = __ldcg(&ubase[(size_t)i0 * 16 + l16]);
        m.x = fmaxf(m.x, a.x); m.y = fmaxf(m.y, a.y);
        m.z = fmaxf(m.z, a.z); m.w = fmaxf(m.w, a.w);
    }

    float px = pos[n * 3 + 0], py = pos[n * 3 + 1], pz = pos[n * 3 + 2];
    int k0 = 4 * l16;
    float4 hh = make_float4(0.f, 0.f, 0.f, 0.f);
    if (e > s) {
        hh.x = m.x - (px * Wp[k0 + 0][0] + py * Wp[k0 + 0][1] + pz * Wp[k0 + 0][2]);
        hh.y = m.y - (px * Wp[k0 + 1][0] + py * Wp[k0 + 1][1] + pz * Wp[k0 + 1][2]);
        hh.z = m.z - (px * Wp[k0 + 2][0] + py * Wp[k0 + 2][1] + pz * Wp[k0 + 2][2]);
        hh.w = m.w - (px * Wp[k0 + 3][0] + py * Wp[k0 + 3][1] + pz * Wp[k0 + 3][2]);
    }

    float sum = hh.x + hh.y + hh.z + hh.w;
    float sq  = hh.x * hh.x + hh.y * hh.y + hh.z * hh.z + hh.w * hh.w;
    #pragma unroll
    for (int o = 8; o > 0; o >>= 1) {
        sum += __shfl_xor_sync(0xffffffffu, sum, o);
        sq  += __shfl_xor_sync(0xffffffffu, sq, o);
    }
    float mean = sum * (1.0f / 64.0f);
    float var  = fmaxf(sq * (1.0f / 64.0f) - mean * mean, 0.f);
    float rstd = rsqrtf(var + 1e-5f);
    float4 o4;
    o4.x = fmaxf((hh.x - mean) * rstd * gs[k0 + 0] + bs[k0 + 0], 0.f);
    o4.y = fmaxf((hh.y - mean) * rstd * gs[k0 + 1] + bs[k0 + 1], 0.f);
    o4.z = fmaxf((hh.z - mean) * rstd * gs[k0 + 2] + bs[k0 + 2], 0.f);
    o4.w = fmaxf((hh.w - mean) * rstd * gs[k0 + 3] + bs[k0 + 3], 0.f);
    *(float4*)&g_z[(size_t)n * ZDIM + layer * 64 + k0] = o4;
}

// ---------------- final LN(320) + MLP: 256 threads, 32-node tile, acc[16]/thread ----------------
#define SMEM_MLP 82176
__global__ __launch_bounds__(256) void k_mlp(const float* __restrict__ b1,
                                             const float* __restrict__ b2,
                                             const float* __restrict__ b3,
                                             const float* __restrict__ w4,
                                             const float* __restrict__ b4,
                                             const float* __restrict__ scale,
                                             float* __restrict__ out) {
    extern __shared__ float sm[];
    float* zsh = sm;                 // 32*320 = 10240
    float* h1s = sm + 10240;         // 32*128 = 4096
    float* h2s = sm + 14336;         // 32*128 = 4096
    float* h3s = sm + 18432;         // 32*64  = 2048
    float* meansh = sm + 20480;      // 32
    float* rstdsh = sm + 20512;      // 32

    int tid = threadIdx.x;
    int grp = tid >> 7;              // node half: 0 -> nodes 0..15, 1 -> 16..31
    int k = tid & 127;               // output channel
    int n0 = blockIdx.x * 32;        // last block reads zeroed pad rows of g_z

    {
        const float4* src = (const float4*)&g_z[(size_t)n0 * ZDIM];
        float4* dst = (float4*)zsh;
        for (int i = tid; i < 2560; i += 256) dst[i] = src[i];
    }
    __syncthreads();

    // LN stats: 8 threads per node over 320 values
    {
        int node = tid >> 3, j = tid & 7;
        float s = 0.f, sq = 0.f;
        for (int c = j; c < 320; c += 8) {
            float v = zsh[node * 320 + c];
            s += v; sq += v * v;
        }
        #pragma unroll
        for (int o = 4; o > 0; o >>= 1) {
            s  += __shfl_down_sync(0xffffffffu, s, o, 8);
            sq += __shfl_down_sync(0xffffffffu, sq, o, 8);
        }
        if (j == 0) {
            float mean = s * (1.0f / 320.0f);
            float var  = fmaxf(sq * (1.0f / 320.0f) - mean * mean, 0.f);
            meansh[node] = mean;
            rstdsh[node] = rsqrtf(var + 1e-5f);
        }
    }
    __syncthreads();
    for (int i = tid; i < 2560; i += 256) {
        int nn = i / 80;
        float mean = meansh[nn], rstd = rstdsh[nn];
        float4 v = ((float4*)zsh)[i];
        v.x = (v.x - mean) * rstd; v.y = (v.y - mean) * rstd;
        v.z = (v.z - mean) * rstd; v.w = (v.w - mean) * rstd;
        ((float4*)zsh)[i] = v;
    }
    __syncthreads();

    ull acc[16];
    const ull* w1p = (const ull*)g_w1P;
    const ull* w2p = (const ull*)g_w2P;
    const ull* w3p = (const ull*)g_w3P;
    float* zg  = zsh + grp * 16 * 320;
    float* h1g = h1s + grp * 16 * 128;
    float* h2g = h2s + grp * 16 * 128;
    float* h3g = h3s + grp * 16 * 64;

    // layer 1: 320 -> 128
    {
        ull binit = pack2(b1[k], 0.f);
        #pragma unroll
        for (int nn = 0; nn < 16; nn++) acc[nn] = binit;
        for (int c = 0; c < 320; c += 4) {
            int c2 = c >> 1;
            ull w01 = w1p[c2 * 128 + k];
            ull w23 = w1p[(c2 + 1) * 128 + k];
            #pragma unroll
            for (int nn = 0; nn < 16; nn++) {
                ulonglong2 z = *(const ulonglong2*)&zg[nn * 320 + c];
                acc[nn] = fma2(z.x, w01, acc[nn]);
                acc[nn] = fma2(z.y, w23, acc[nn]);
            }
        }
        #pragma unroll
        for (int nn = 0; nn < 16; nn++) h1g[nn * 128 + k] = fmaxf(sum2(acc[nn]), 0.f);
    }
    __syncthreads();

    // layer 2: 128 -> 128
    {
        ull binit = pack2(b2[k], 0.f);
        #pragma unroll
        for (int nn = 0; nn < 16; nn++) acc[nn] = binit;
        for (int c = 0; c < 128; c += 4) {
            int c2 = c >> 1;
            ull w01 = w2p[c2 * 128 + k];
            ull w23 = w2p[(c2 + 1) * 128 + k];
            #pragma unroll
            for (int nn = 0; nn < 16; nn++) {
                ulonglong2 z = *(const ulonglong2*)&h1g[nn * 128 + c];
                acc[nn] = fma2(z.x, w01, acc[nn]);
                acc[nn] = fma2(z.y, w23, acc[nn]);
            }
        }
        #pragma unroll
        for (int nn = 0; nn < 16; nn++) h2g[nn * 128 + k] = fmaxf(sum2(acc[nn]), 0.f);
    }
    __syncthreads();

    // layer 3: 128 -> 64 (k < 64 in each group)
    if (k < 64) {
        ull binit = pack2(b3[k], 0.f);
        #pragma unroll
        for (int nn = 0; nn < 16; nn++) acc[nn] = binit;
        for (int c = 0; c < 128; c += 4) {
            int c2 = c >> 1;
            ull w01 = w3p[c2 * 64 + k];
            ull w23 = w3p[(c2 + 1) * 64 + k];
            #pragma unroll
            for (int nn = 0; nn < 16; nn++) {
                ulonglong2 z = *(const ulonglong2*)&h2g[nn * 128 + c];
                acc[nn] = fma2(z.x, w01, acc[nn]);
                acc[nn] = fma2(z.y, w23, acc[nn]);
            }
        }
        #pragma unroll
        for (int nn = 0; nn < 16; nn++) h3g[nn * 64 + k] = fmaxf(sum2(acc[nn]), 0.f);
    }
    __syncthreads();

    // layer 4: 64 -> 2, * scale  (64 threads: 32 nodes x 2 outputs)
    if (tid < 64) {
        int nn = tid >> 1, o = tid & 1;
        int n = n0 + nn;
        if (n < N_NODES) {
            float a = b4[o];
            const float* wrow = &w4[o * 64];
            #pragma unroll 8
            for (int c = 0; c < 64; c++) a += h3s[nn * 64 + c] * wrow[c];
            out[(size_t)n * 2 + o] = a * scale[o];
        }
    }
}

// ---------------- launch ----------------
extern "C" void kernel_launch(void* const* d_in, const int* in_sizes, int n_in,
                              void* d_out, int out_size) {
    const float* x     = (const float*)d_in[0];
    const float* pos   = (const float*)d_in[1];
    const int*   ei    = (const int*)d_in[2];
    const float* W0    = (const float*)d_in[3];
    const float* Ws    = (const float*)d_in[4];
    const float* ln_g  = (const float*)d_in[5];
    const float* ln_b  = (const float*)d_in[6];
    const float* w1    = (const float*)d_in[7];
    const float* b1    = (const float*)d_in[8];
    const float* w2    = (const float*)d_in[9];
    const float* b2    = (const float*)d_in[10];
    const float* w3    = (const float*)d_in[11];
    const float* b3    = (const float*)d_in[12];
    const float* w4    = (const float*)d_in[13];
    const float* b4    = (const float*)d_in[14];
    const float* scale = (const float*)d_in[15];
    float* out = (float*)d_out;

    cudaFuncSetAttribute(k_mlp, cudaFuncAttributeMaxDynamicSharedMemorySize, SMEM_MLP);

    const int TGRID = (N_NODES + 31) / 32;  // 1563

    k_prep<<<3290, 256>>>(ei, W0, Ws, w1, w2, w3);                 // #1 (hist + quant + transpose)
    k_scan_local<<<SCAN_BLK, 512>>>();                             // #2
    k_scan_add<<<SCAN_BLK, 512>>>();                               // #3
    k_transform0<<<TGRID, 256>>>(x, pos);                          // #4  <- profiled
    k_scatter<<<(N_EDGES + 255) / 256, 256>>>(ei);                 // #5
    k_aggregate<<<N_NODES / 16, 256>>>(pos, ln_g, ln_b, 0, 4);     // #6

    for (int i = 1; i < 5; i++) {
        k_transform<<<TGRID, 256>>>(pos, i);
        k_aggregate<<<N_NODES / 16, 256>>>(pos, ln_g, ln_b, i, 67);
    }

    k_mlp<<<(N_NODES + 31) / 32, 256, SMEM_MLP>>>(b1, b2, b3, w4, b4, scale, out);
}

// round 11
// speedup vs baseline: 1.1854x; 1.1854x over previous
#include <cuda_runtime.h>
#include <cuda_bf16.h>
#include <cuda_fp16.h>
#include <cfloat>
#include <cstdint>

#define N_NODES 50000
#define N_EDGES 800000
#define HID 64
#define ZDIM 320
#define WSTRIDE 68                 // padded W row (64x68, zeros in pad)
#define WSZ (64 * WSTRIDE)
#define SCAN_BLK 98                // ceil(50000/512)

typedef unsigned long long ull;

// ---------------- device scratch ----------------
__device__ __half g_uh[N_NODES * HID];     // u stored fp16 (gather payload)
__device__ float g_z[N_NODES * ZDIM];
__device__ int   g_cnt[N_NODES];           // INVARIANT: all-zero at kernel_launch entry
__device__ int   g_off[N_NODES + 1];
__device__ int   g_cur[N_NODES];
__device__ int   g_csr[N_EDGES];
__device__ int   g_bsum[SCAN_BLK];
__device__ float g_Wq[5 * WSZ];            // all 5 quantized layer weights
__device__ float g_w1P[320 * 128];         // paired [c/2][128] float2 layout
__device__ float g_w2P[128 * 128];
__device__ float g_w3P[128 * 64];

// ---------------- f32x2 helpers ----------------
__device__ __forceinline__ ull fma2(ull a, ull b, ull c) {
    ull d;
    asm("fma.rn.f32x2 %0, %1, %2, %3;" : "=l"(d) : "l"(a), "l"(b), "l"(c));
    return d;
}
__device__ __forceinline__ ull pack2(float lo, float hi) {
    ull r;
    asm("mov.b64 %0, {%1, %2};" : "=l"(r) : "f"(lo), "f"(hi));
    return r;
}
__device__ __forceinline__ float sum2(ull a) {
    float lo, hi;
    asm("mov.b64 {%0, %1}, %2;" : "=f"(lo), "=f"(hi) : "l"(a));
    return lo + hi;
}

// ---------------- CSR construction ----------------
__global__ void k_hist(const int* __restrict__ ei) {
    int e = blockIdx.x * blockDim.x + threadIdx.x;
    if (e < N_EDGES) atomicAdd(&g_cnt[ei[N_EDGES + e]], 1);
}

__global__ void k_scan_local() {
    __shared__ int wsums[16];
    int b = blockIdx.x, tid = threadIdx.x, lane = tid & 31, wid = tid >> 5;
    int i = b * 512 + tid;
    int v = (i < N_NODES) ? g_cnt[i] : 0;
    int x = v;
    #pragma unroll
    for (int o = 1; o < 32; o <<= 1) {
        int y = __shfl_up_sync(0xffffffffu, x, o);
        if (lane >= o) x += y;
    }
    if (lane == 31) wsums[wid] = x;
    __syncthreads();
    if (wid == 0 && lane < 16) {
        int w = wsums[lane];
        int xs = w;
        #pragma unroll
        for (int o = 1; o < 16; o <<= 1) {
            int y = __shfl_up_sync(0xffffu, xs, o);
            if (lane >= o) xs += y;
        }
        wsums[lane] = xs - w;
    }
    __syncthreads();
    int excl = x - v + wsums[wid];
    if (i < N_NODES) g_off[i] = excl;
    if (tid == 511) g_bsum[b] = excl + v;
}

__global__ void k_scan_add() {
    __shared__ int part[4];
    int b = blockIdx.x, tid = threadIdx.x, lane = tid & 31, wid = tid >> 5;
    int v = 0;
    if (tid < b) v = g_bsum[tid];      // b <= 97 < 128
    if (tid < 128) {
        #pragma unroll
        for (int o = 16; o > 0; o >>= 1) v += __shfl_xor_sync(0xffffffffu, v, o);
        if (lane == 0) part[wid] = v;
    }
    __syncthreads();
    int add = part[0] + part[1] + part[2] + part[3];
    int i = b * 512 + tid;
    if (i < N_NODES) {
        int o = g_off[i] + add;
        g_off[i] = o;
        g_cur[i] = o;
        g_cnt[i] = 0;   // restore zero-invariant for next replay
    }
    if (i == 0) g_off[N_NODES] = N_EDGES;
}

__global__ void k_scatter(const int* __restrict__ ei) {
    int e = blockIdx.x * blockDim.x + threadIdx.x;
    if (e < N_EDGES) {
        int d = ei[N_EDGES + e];
        int p = atomicAdd(&g_cur[d], 1);
        g_csr[p] = ei[e];
    }
}

// ---------------- weight prep (fake-quant + MLP-weight transpose) ----------------
__global__ void k_quant_prep(const float* __restrict__ W0, const float* __restrict__ Ws,
                             const float* __restrict__ w1, const float* __restrict__ w2,
                             const float* __restrict__ w3) {
    int b = blockIdx.x, tid = threadIdx.x;
    if (b < 5) {
        __shared__ float red[256];
        const float* W = (b == 0) ? W0 : (Ws + (size_t)(b - 1) * 64 * 67);
        int cols = (b == 0) ? 4 : 67;
        int n = 64 * cols;
        float* dst = g_Wq + b * WSZ;

        float m = 0.f;
        for (int i = tid; i < n; i += 256) m = fmaxf(m, fabsf(W[i]));
        red[tid] = m;
        __syncthreads();
        for (int s = 128; s > 0; s >>= 1) {
            if (tid < s) red[tid] = fmaxf(red[tid], red[tid + s]);
            __syncthreads();
        }
        float sc = fmaxf(red[0] * (1.0f / 127.0f), 1e-8f);
        for (int i = tid; i < WSZ; i += 256) dst[i] = 0.0f;
        __syncthreads();
        for (int i = tid; i < n; i += 256) {
            int k = i / cols, c = i % cols;
            float q = rintf(W[i] / sc);
            q = fminf(fmaxf(q, -127.0f), 127.0f) * sc;
            dst[k * WSTRIDE + c] = q;
        }
    } else {
        int i = (b - 5) * 256 + tid;
        if (i < 40960) { int r = i / 320, c = i % 320; g_w1P[((c >> 1) * 128 + r) * 2 + (c & 1)] = w1[i]; }
        if (i < 16384) { int r = i / 128, c = i % 128; g_w2P[((c >> 1) * 128 + r) * 2 + (c & 1)] = w2[i]; }
        if (i <  8192) { int r = i / 128, c = i % 128; g_w3P[((c >> 1) * 64  + r) * 2 + (c & 1)] = w3[i]; }
    }
}

// ---------------- layer-0 transform ----------------
__global__ __launch_bounds__(256) void k_transform0(const float* __restrict__ x,
                                                    const float* __restrict__ pos) {
    __shared__ float4 Wsh[64];
    __shared__ float  xs[32];
    __shared__ float  ps[96];
    int tid = threadIdx.x;
    int nbase = blockIdx.x * 32;
    if (tid < 64) {
        const float* wr = g_Wq + tid * WSTRIDE;
        Wsh[tid] = make_float4(wr[0], wr[1], wr[2], wr[3]);
    } else if (tid < 96) {
        int n = nbase + (tid - 64);
        xs[tid - 64] = (n < N_NODES) ? x[n] : 0.f;
    } else if (tid < 192) {
        int j = tid - 96;
        int gi = nbase * 3 + j;
        ps[j] = (gi < N_NODES * 3) ? pos[gi] : 0.f;
    }
    __syncthreads();
    int k = tid & 63, grp = tid >> 6;
    float4 w = Wsh[k];
    #pragma unroll
    for (int j = 0; j < 8; j++) {
        int nn = grp * 8 + j;
        int n = nbase + nn;
        if (n < N_NODES) {
            float r = w.x * xs[nn] + w.y * ps[3 * nn] + w.z * ps[3 * nn + 1] + w.w * ps[3 * nn + 2];
            g_uh[(size_t)n * HID + k] = __float2half(r);
        }
    }
}

// ---------------- layers 1-4 transform ----------------
__global__ __launch_bounds__(256) void k_transform(const float* __restrict__ pos, int layer) {
    constexpr int C4 = 17;
    __shared__ float Wsh[WSZ];
    __shared__ float fsh[32][WSTRIDE];
    int tid = threadIdx.x;
    int k = tid & 63, grp = tid >> 6;
    const float* Wsrc = g_Wq + layer * WSZ;
    {
        const float4* s4 = (const float4*)Wsrc;
        float4* d4 = (float4*)Wsh;
        #pragma unroll
        for (int i = tid; i < WSZ / 4; i += 256) d4[i] = s4[i];
    }
    int nbase = blockIdx.x * 32;
    const float* h = g_z + (size_t)(layer - 1) * HID;
    #pragma unroll
    for (int i = tid; i < 32 * 64; i += 256) {
        int nn = i >> 6, c = i & 63;
        int gn = nbase + nn;
        fsh[nn][c] = (gn < N_NODES) ? h[(size_t)gn * ZDIM + c] : 0.f;
    }
    if (tid < 128) {
        int nn = tid >> 2, j = tid & 3;
        int gn = nbase + nn;
        float v = 0.f;
        if (j < 3 && gn < N_NODES) v = pos[gn * 3 + j];
        fsh[nn][64 + j] = v;
    }
    __syncthreads();
    ull w2r[C4 * 2];
    #pragma unroll
    for (int c4 = 0; c4 < C4; c4++) {
        ulonglong2 wv = *(const ulonglong2*)&Wsh[k * WSTRIDE + 4 * c4];
        w2r[2 * c4] = wv.x; w2r[2 * c4 + 1] = wv.y;
    }
    ull acc[8];
    #pragma unroll
    for (int j = 0; j < 8; j++) acc[j] = 0;
    #pragma unroll
    for (int c4 = 0; c4 < C4; c4++) {
        ull w01 = w2r[2 * c4], w23 = w2r[2 * c4 + 1];
        #pragma unroll
        for (int j = 0; j < 8; j++) {
            ulonglong2 f = *(const ulonglong2*)&fsh[grp * 8 + j][4 * c4];
            acc[j] = fma2(f.x, w01, acc[j]);
            acc[j] = fma2(f.y, w23, acc[j]);
        }
    }
    #pragma unroll
    for (int j = 0; j < 8; j++) {
        int n = nbase + grp * 8 + j;
        if (n < N_NODES) g_uh[(size_t)n * HID + k] = __float2half(sum2(acc[j]));
    }
}

// ---------------- aggregation: 2 nodes/warp, 16 lanes x half2x2 (8B/lane) ----------------
__global__ __launch_bounds__(256) void k_aggregate(const float* __restrict__ pos,
                                                   const float* __restrict__ ln_g,
                                                   const float* __restrict__ ln_b,
                                                   int layer, int cols) {
    __shared__ float Wp[64][3];
    __shared__ float gs[64], bs[64];
    int tid = threadIdx.x;
    if (tid < 64) { gs[tid] = ln_g[layer * 64 + tid]; bs[tid] = ln_b[layer * 64 + tid]; }
    const float* Wsrc = g_Wq + layer * WSZ;
    for (int i = tid; i < 192; i += 256) {
        int k = i / 3, j = i % 3;
        Wp[k][j] = Wsrc[k * WSTRIDE + (cols - 3) + j];
    }
    __syncthreads();

    int wid = tid >> 5, lane = tid & 31;
    int half = lane >> 4, l16 = lane & 15;
    int n = blockIdx.x * 16 + wid * 2 + half;      // grid*16 == N_NODES exactly
    int s = g_off[n], e = g_off[n + 1];
    const uint2* ubase = (const uint2*)g_uh;        // row = 16 uint2 (64 halfs)

    __half2 M0 = __float2half2_rn(-65504.f);
    __half2 M1 = __float2half2_rn(-65504.f);
    int p = s;
    for (; p + 8 <= e; p += 8) {
        int i0 = g_csr[p],     i1 = g_csr[p + 1], i2 = g_csr[p + 2], i3 = g_csr[p + 3];
        int i4 = g_csr[p + 4], i5 = g_csr[p + 5], i6 = g_csr[p + 6], i7 = g_csr[p + 7];
        uint2 a = __ldcg(&ubase[(size_t)i0 * 16 + l16]);
        uint2 b = __ldcg(&ubase[(size_t)i1 * 16 + l16]);
        uint2 c = __ldcg(&ubase[(size_t)i2 * 16 + l16]);
        uint2 d = __ldcg(&ubase[(size_t)i3 * 16 + l16]);
        uint2 f = __ldcg(&ubase[(size_t)i4 * 16 + l16]);
        uint2 g = __ldcg(&ubase[(size_t)i5 * 16 + l16]);
        uint2 h = __ldcg(&ubase[(size_t)i6 * 16 + l16]);
        uint2 q = __ldcg(&ubase[(size_t)i7 * 16 + l16]);
        M0 = __hmax2(M0, __hmax2(__hmax2(*(__half2*)&a.x, *(__half2*)&b.x),
                                 __hmax2(*(__half2*)&c.x, *(__half2*)&d.x)));
        M0 = __hmax2(M0, __hmax2(__hmax2(*(__half2*)&f.x, *(__half2*)&g.x),
                                 __hmax2(*(__half2*)&h.x, *(__half2*)&q.x)));
        M1 = __hmax2(M1, __hmax2(__hmax2(*(__half2*)&a.y, *(__half2*)&b.y),
                                 __hmax2(*(__half2*)&c.y, *(__half2*)&d.y)));
        M1 = __hmax2(M1, __hmax2(__hmax2(*(__half2*)&f.y, *(__half2*)&g.y),
                                 __hmax2(*(__half2*)&h.y, *(__half2*)&q.y)));
    }
    for (; p + 4 <= e; p += 4) {
        int i0 = g_csr[p], i1 = g_csr[p + 1], i2 = g_csr[p + 2], i3 = g_csr[p + 3];
        uint2 a = __ldcg(&ubase[(size_t)i0 * 16 + l16]);
        uint2 b = __ldcg(&ubase[(size_t)i1 * 16 + l16]);
        uint2 c = __ldcg(&ubase[(size_t)i2 * 16 + l16]);
        uint2 d = __ldcg(&ubase[(size_t)i3 * 16 + l16]);
        M0 = __hmax2(M0, __hmax2(__hmax2(*(__half2*)&a.x, *(__half2*)&b.x),
                                 __hmax2(*(__half2*)&c.x, *(__half2*)&d.x)));
        M1 = __hmax2(M1, __hmax2(__hmax2(*(__half2*)&a.y, *(__half2*)&b.y),
                                 __hmax2(*(__half2*)&c.y, *(__half2*)&d.y)));
    }
    for (; p < e; p++) {
        int i0 = g_csr[p];
        uint2 a = __ldcg(&ubase[(size_t)i0 * 16 + l16]);
        M0 = __hmax2(M0, *(__half2*)&a.x);
        M1 = __hmax2(M1, *(__half2*)&a.y);
    }

    float2 f0 = __half22float2(M0);
    float2 f1 = __half22float2(M1);

    float px = pos[n * 3 + 0], py = pos[n * 3 + 1], pz = pos[n * 3 + 2];
    int k0 = 4 * l16;
    float4 hh = make_float4(0.f, 0.f, 0.f, 0.f);
    if (e > s) {
        hh.x = f0.x - (px * Wp[k0 + 0][0] + py * Wp[k0 + 0][1] + pz * Wp[k0 + 0][2]);
        hh.y = f0.y - (px * Wp[k0 + 1][0] + py * Wp[k0 + 1][1] + pz * Wp[k0 + 1][2]);
        hh.z = f1.x - (px * Wp[k0 + 2][0] + py * Wp[k0 + 2][1] + pz * Wp[k0 + 2][2]);
        hh.w = f1.y - (px * Wp[k0 + 3][0] + py * Wp[k0 + 3][1] + pz * Wp[k0 + 3][2]);
    }

    // LayerNorm over 64 channels within the 16-lane half-warp
    float sum = hh.x + hh.y + hh.z + hh.w;
    float sq  = hh.x * hh.x + hh.y * hh.y + hh.z * hh.z + hh.w * hh.w;
    #pragma unroll
    for (int o = 8; o > 0; o >>= 1) {
        sum += __shfl_xor_sync(0xffffffffu, sum, o);
        sq  += __shfl_xor_sync(0xffffffffu, sq, o);
    }
    float mean = sum * (1.0f / 64.0f);
    float var  = fmaxf(sq * (1.0f / 64.0f) - mean * mean, 0.f);
    float rstd = rsqrtf(var + 1e-5f);
    float4 o4;
    o4.x = fmaxf((hh.x - mean) * rstd * gs[k0 + 0] + bs[k0 + 0], 0.f);
    o4.y = fmaxf((hh.y - mean) * rstd * gs[k0 + 1] + bs[k0 + 1], 0.f);
    o4.z = fmaxf((hh.z - mean) * rstd * gs[k0 + 2] + bs[k0 + 2], 0.f);
    o4.w = fmaxf((hh.w - mean) * rstd * gs[k0 + 3] + bs[k0 + 3], 0.f);
    *(float4*)&g_z[(size_t)n * ZDIM + layer * 64 + k0] = o4;
}

// ---------------- final LN(320) + MLP 320->128->128->64->2, FFMA2, 16-node tile ----------------
__global__ __launch_bounds__(128) void k_mlp(const float* __restrict__ b1,
                                             const float* __restrict__ b2,
                                             const float* __restrict__ b3,
                                             const float* __restrict__ w4,
                                             const float* __restrict__ b4,
                                             const float* __restrict__ scale,
                                             float* __restrict__ out) {
    __shared__ float zsh[16 * 320];
    __shared__ float h1s[16 * 128];
    __shared__ float h2s[16 * 128];
    __shared__ float h3s[16 * 64];
    __shared__ float meansh[16], rstdsh[16];

    int tid = threadIdx.x;
    int n0 = blockIdx.x * 16;

    for (int i = tid; i < 16 * 320; i += 128) zsh[i] = g_z[(size_t)n0 * ZDIM + i];
    __syncthreads();

    {
        int node = tid >> 3, j = tid & 7;
        float s = 0.f, sq = 0.f;
        for (int c = j; c < 320; c += 8) {
            float v = zsh[node * 320 + c];
            s += v; sq += v * v;
        }
        #pragma unroll
        for (int o = 4; o > 0; o >>= 1) {
            s  += __shfl_down_sync(0xffffffffu, s, o, 8);
            sq += __shfl_down_sync(0xffffffffu, sq, o, 8);
        }
        if (j == 0) {
            float mean = s * (1.0f / 320.0f);
            float var  = fmaxf(sq * (1.0f / 320.0f) - mean * mean, 0.f);
            meansh[node] = mean;
            rstdsh[node] = rsqrtf(var + 1e-5f);
        }
    }
    __syncthreads();
    for (int i = tid; i < 16 * 320; i += 128) {
        int nn = i / 320;
        zsh[i] = (zsh[i] - meansh[nn]) * rstdsh[nn];
    }
    __syncthreads();

    ull acc[16];
    const ull* w1p = (const ull*)g_w1P;
    const ull* w2p = (const ull*)g_w2P;
    const ull* w3p = (const ull*)g_w3P;

    // layer 1: 320 -> 128
    {
        ull binit = pack2(b1[tid], 0.f);
        #pragma unroll
        for (int nn = 0; nn < 16; nn++) acc[nn] = binit;
        for (int c = 0; c < 320; c += 4) {
            int c2 = c >> 1;
            ull w01 = w1p[c2 * 128 + tid];
            ull w23 = w1p[(c2 + 1) * 128 + tid];
            #pragma unroll
            for (int nn = 0; nn < 16; nn++) {
                ulonglong2 z = *(const ulonglong2*)&zsh[nn * 320 + c];
                acc[nn] = fma2(z.x, w01, acc[nn]);
                acc[nn] = fma2(z.y, w23, acc[nn]);
            }
        }
        #pragma unroll
        for (int nn = 0; nn < 16; nn++) h1s[nn * 128 + tid] = fmaxf(sum2(acc[nn]), 0.f);
    }
    __syncthreads();

    // layer 2: 128 -> 128
    {
        ull binit = pack2(b2[tid], 0.f);
        #pragma unroll
        for (int nn = 0; nn < 16; nn++) acc[nn] = binit;
        for (int c = 0; c < 128; c += 4) {
            int c2 = c >> 1;
            ull w01 = w2p[c2 * 128 + tid];
            ull w23 = w2p[(c2 + 1) * 128 + tid];
            #pragma unroll
            for (int nn = 0; nn < 16; nn++) {
                ulonglong2 z = *(const ulonglong2*)&h1s[nn * 128 + c];
                acc[nn] = fma2(z.x, w01, acc[nn]);
                acc[nn] = fma2(z.y, w23, acc[nn]);
            }
        }
        #pragma unroll
        for (int nn = 0; nn < 16; nn++) h2s[nn * 128 + tid] = fmaxf(sum2(acc[nn]), 0.f);
    }
    __syncthreads();

    // layer 3: 128 -> 64
    if (tid < 64) {
        ull binit = pack2(b3[tid], 0.f);
        #pragma unroll
        for (int nn = 0; nn < 16; nn++) acc[nn] = binit;
        for (int c = 0; c < 128; c += 4) {
            int c2 = c >> 1;
            ull w01 = w3p[c2 * 64 + tid];
            ull w23 = w3p[(c2 + 1) * 64 + tid];
            #pragma unroll
            for (int nn = 0; nn < 16; nn++) {
                ulonglong2 z = *(const ulonglong2*)&h2s[nn * 128 + c];
                acc[nn] = fma2(z.x, w01, acc[nn]);
                acc[nn] = fma2(z.y, w23, acc[nn]);
            }
        }
        #pragma unroll
        for (int nn = 0; nn < 16; nn++) h3s[nn * 64 + tid] = fmaxf(sum2(acc[nn]), 0.f);
    }
    __syncthreads();

    // layer 4: 64 -> 2, * scale
    if (tid < 32) {
        int nn = tid >> 1, o = tid & 1;
        float a = b4[o];
        const float* wrow = &w4[o * 64];
        #pragma unroll 8
        for (int c = 0; c < 64; c++) a += h3s[nn * 64 + c] * wrow[c];
        out[(size_t)(n0 + nn) * 2 + o] = a * scale[o];
    }
}

// ---------------- launch ----------------
extern "C" void kernel_launch(void* const* d_in, const int* in_sizes, int n_in,
                              void* d_out, int out_size) {
    const float* x     = (const float*)d_in[0];
    const float* pos   = (const float*)d_in[1];
    const int*   ei    = (const int*)d_in[2];
    const float* W0    = (const float*)d_in[3];
    const float* Ws    = (const float*)d_in[4];
    const float* ln_g  = (const float*)d_in[5];
    const float* ln_b  = (const float*)d_in[6];
    const float* w1    = (const float*)d_in[7];
    const float* b1    = (const float*)d_in[8];
    const float* w2    = (const float*)d_in[9];
    const float* b2    = (const float*)d_in[10];
    const float* w3    = (const float*)d_in[11];
    const float* b3    = (const float*)d_in[12];
    const float* w4    = (const float*)d_in[13];
    const float* b4    = (const float*)d_in[14];
    const float* scale = (const float*)d_in[15];
    float* out = (float*)d_out;

    const int TGRID = (N_NODES + 31) / 32;  // 1563

    k_hist<<<(N_EDGES + 255) / 256, 256>>>(ei);                    // #1
    k_quant_prep<<<165, 256>>>(W0, Ws, w1, w2, w3);                // #2
    k_scan_local<<<SCAN_BLK, 512>>>();                             // #3
    k_transform0<<<TGRID, 256>>>(x, pos);                          // #4  <- profiled
    k_scan_add<<<SCAN_BLK, 512>>>();                               // #5
    k_scatter<<<(N_EDGES + 255) / 256, 256>>>(ei);                 // #6
    k_aggregate<<<N_NODES / 16, 256>>>(pos, ln_g, ln_b, 0, 4);     // #7

    for (int i = 1; i < 5; i++) {
        k_transform<<<TGRID, 256>>>(pos, i);
        k_aggregate<<<N_NODES / 16, 256>>>(pos, ln_g, ln_b, i, 67);
    }

    k_mlp<<<N_NODES / 16, 128>>>(b1, b2, b3, w4, b4, scale, out);
}